// round 13
// baseline (speedup 1.0000x reference)
#include <cuda_runtime.h>

// x: (B=64, C=128, T=10000) float32, row-major.
#define B_DIM 64
#define C_DIM 128
#define T_DIM 10000
#define T4    2500

// Chunked fusion: 8 chunks of 8 batches (41 MB) — chunk fits L2 alongside the
// next chunk being prefetched by phase A (84 MB total < 126 MB L2).
#define NCHUNK      8
#define B_PER_CHUNK (B_DIM / NCHUNK)          // 8
#define CHUNK_QUADS (B_PER_CHUNK * T4)        // 20000 float4
#define CHUNK_ROWS  (B_PER_CHUNK * C_DIM)     // 1024

#define THREADS 256
#define GRID    592     // 148 SMs x 4 CTAs — all co-resident (<=64 regs, 4.2KB smem)

// Phase A geometry (channel-split mean): 32 quads x 8 groups x 16 channels.
#define A_QPC  32
#define A_GPC  8
#define A_CPG  16
#define A_JOBS (CHUNK_QUADS / A_QPC)          // 625

__device__ float    g_mu[B_DIM * T_DIM];      // 2.56 MB, L2-resident
__device__ unsigned g_bar_count = 0;
__device__ unsigned g_bar_gen   = 0;

__device__ __forceinline__ unsigned ld_cg_u32(const unsigned* p) {
    unsigned v;
    asm volatile("ld.global.cg.u32 %0, [%1];" : "=r"(v) : "l"(p));
    return v;
}

// Software grid barrier: atomic arrival counter + generation flag.
// Safe because all GRID CTAs are co-resident. gen is read BEFORE arriving.
__device__ __forceinline__ void grid_sync() {
    __syncthreads();
    if (threadIdx.x == 0) {
        __threadfence();
        unsigned gen  = ld_cg_u32(&g_bar_gen);
        unsigned prev = atomicAdd(&g_bar_count, 1u);
        if (prev == (unsigned)gridDim.x - 1u) {
            g_bar_count = 0;
            __threadfence();
            atomicAdd(&g_bar_gen, 1u);
        } else {
            while (ld_cg_u32(&g_bar_gen) == gen) { __nanosleep(64); }
        }
    }
    __syncthreads();
}

// ---------------------------------------------------------------------------
// Phase A: mu for one chunk. Default (evict-normal) loads — the whole chunk
// must stay L2-resident for phase B. Lanes = consecutive quads (512B/warp).
// ---------------------------------------------------------------------------
__device__ __forceinline__ void phase_mu(const float* __restrict__ x, int chunk,
                                         float4 (*part)[A_QPC]) {
    const int ql = threadIdx.x & 31;
    const int g  = threadIdx.x >> 5;

    for (int j = blockIdx.x; j < A_JOBS; j += GRID) {
        const int q  = chunk * CHUNK_QUADS + j * A_QPC + ql;
        const int b  = q / T4;
        const int i4 = q - b * T4;

        const float4* __restrict__ xp =
            reinterpret_cast<const float4*>(x)
            + ((size_t)b * C_DIM + (size_t)g * A_CPG) * T4 + i4;

        float sx = 0.f, sy = 0.f, sz = 0.f, sw = 0.f;
#pragma unroll
        for (int c = 0; c < A_CPG; ++c) {
            float4 v = xp[(size_t)c * T4];        // evict-normal: keep in L2
            sx += v.x; sy += v.y; sz += v.z; sw += v.w;
        }
        float4 p; p.x = sx; p.y = sy; p.z = sz; p.w = sw;
        part[g][ql] = p;
        __syncthreads();

        if (threadIdx.x < A_QPC) {
            float4 a = part[0][ql];
#pragma unroll
            for (int gg = 1; gg < A_GPC; ++gg) {
                float4 t = part[gg][ql];
                a.x += t.x; a.y += t.y; a.z += t.z; a.w += t.w;
            }
            const float inv = 1.0f / (float)C_DIM;
            a.x *= inv; a.y *= inv; a.z *= inv; a.w *= inv;
            reinterpret_cast<float4*>(g_mu)[(size_t)b * T4 + i4] = a;
        }
        __syncthreads();                           // part reused next job
    }
}

// ---------------------------------------------------------------------------
// Phase B: stats + normalize for one chunk's rows. x/mu come from L2 (loaded
// by phase A of this chunk); pass 2 re-reads them from L1/L2. Output written
// evict-first so the write stream doesn't evict the L2-resident next chunk.
// Row assignment starts from (GRID-1-blockIdx.x) to anti-correlate with
// phase A's job assignment (balances total per-CTA work in the fused loop).
// ---------------------------------------------------------------------------
__device__ __forceinline__ void phase_norm(const float* __restrict__ x,
                                           float* __restrict__ out, int chunk,
                                           float* red_s, float* red_s2,
                                           float* s_stat) {
    for (int r = (GRID - 1) - blockIdx.x; r < CHUNK_ROWS; r += GRID) {
        const int row = chunk * CHUNK_ROWS + r;
        const int b   = row >> 7;

        const float4* __restrict__ xp =
            reinterpret_cast<const float4*>(x) + (size_t)row * T4;
        const float4* __restrict__ mp =
            reinterpret_cast<const float4*>(g_mu) + (size_t)b * T4;

        // Pass 1: accumulate sum / sumsq of d = x - mu (L2 hits; allocate L1
        // for pass-2 reuse).
        float s = 0.f, s2 = 0.f;
        for (int i = threadIdx.x; i < T4; i += THREADS) {
            float4 xv = xp[i];
            float4 mv = mp[i];
            float dx = xv.x - mv.x, dy = xv.y - mv.y;
            float dz = xv.z - mv.z, dw = xv.w - mv.w;
            s  += dx + dy + dz + dw;
            s2 += dx * dx + dy * dy + dz * dz + dw * dw;
        }
#pragma unroll
        for (int o = 16; o > 0; o >>= 1) {
            s  += __shfl_down_sync(0xffffffffu, s,  o);
            s2 += __shfl_down_sync(0xffffffffu, s2, o);
        }
        const int wid = threadIdx.x >> 5;
        const int lid = threadIdx.x & 31;
        if (lid == 0) { red_s[wid] = s; red_s2[wid] = s2; }
        __syncthreads();

        if (threadIdx.x < 32) {
            float a  = (lid < 8) ? red_s[lid]  : 0.f;
            float a2 = (lid < 8) ? red_s2[lid] : 0.f;
#pragma unroll
            for (int o = 4; o > 0; o >>= 1) {
                a  += __shfl_down_sync(0xffffffffu, a,  o);
                a2 += __shfl_down_sync(0xffffffffu, a2, o);
            }
            if (lid == 0) {
                const float invT = 1.0f / (float)T_DIM;
                float mean = a * invT;
                float var  = a2 * invT - mean * mean;
                float sd   = sqrtf(fmaxf(var, 0.0f));
                if (sd == 0.0f) sd = 1.0f;
                s_stat[0] = mean;
                s_stat[1] = 1.0f / sd;
            }
        }
        __syncthreads();

        const float mean = s_stat[0];
        const float invs = s_stat[1];

        // Pass 2: re-read (L1/L2 hits), write normalized output evict-first.
        float4* __restrict__ op =
            reinterpret_cast<float4*>(out) + (size_t)row * T4;
        for (int i = threadIdx.x; i < T4; i += THREADS) {
            float4 xv = __ldcs(xp + i);
            float4 mv = mp[i];
            float4 rr;
            rr.x = (xv.x - mv.x - mean) * invs;
            rr.y = (xv.y - mv.y - mean) * invs;
            rr.z = (xv.z - mv.z - mean) * invs;
            rr.w = (xv.w - mv.w - mean) * invs;
            __stcs(op + i, rr);
        }
        __syncthreads();                           // red arrays reused next row
    }
}

// ---------------------------------------------------------------------------
// Persistent fused kernel. Software-pipelined: A(k+1) overlaps B(k), so
// read-heavy and write-heavy traffic mix, and chunk k stays L2-resident
// while chunk k+1 streams in.
// ---------------------------------------------------------------------------
__global__ __launch_bounds__(THREADS, 4)
void fused_kernel(const float* __restrict__ x, float* __restrict__ out) {
    __shared__ float4 part[A_GPC][A_QPC];          // 4 KB
    __shared__ float  red_s[8], red_s2[8], s_stat[2];

    phase_mu(x, 0, part);
    grid_sync();

    for (int k = 0; k < NCHUNK; ++k) {
        if (k + 1 < NCHUNK) phase_mu(x, k + 1, part);
        phase_norm(x, out, k, red_s, red_s2, s_stat);
        grid_sync();
    }
}

extern "C" void kernel_launch(void* const* d_in, const int* in_sizes, int n_in,
                              void* d_out, int out_size) {
    (void)in_sizes; (void)n_in; (void)out_size;
    const float* x   = (const float*)d_in[0];
    float*       out = (float*)d_out;

    fused_kernel<<<GRID, THREADS>>>(x, out);
}

// round 14
// speedup vs baseline: 1.1955x; 1.1955x over previous
#include <cuda_runtime.h>

// x: (B=64, C=128, T=10000) float32, row-major.
#define B_DIM 64
#define C_DIM 128
#define T_DIM 10000
#define T4    2500

// Chunked producer->consumer: 8 chunks of 8 batches (41 MB each).
// mu_chunk(k) parks chunk k in L2 (evict-normal); norm_chunk(k) consumes it
// immediately (L2 hits) and writes out evict-first. Kernel boundary = sync.
#define NCHUNK      8
#define B_PER_CHUNK (B_DIM / NCHUNK)          // 8
#define CHUNK_QUADS (B_PER_CHUNK * T4)        // 20000 float4
#define CHUNK_ROWS  (B_PER_CHUNK * C_DIM)     // 1024

// K1 (mu) geometry: 8-way channel split, 32 quads x 8 groups x 16 channels.
#define K1_THREADS 256
#define K1_QPC  32
#define K1_GPC  8
#define K1_CPG  16
#define K1_GRID (CHUNK_QUADS / K1_QPC)        // 625 CTAs per chunk

// K2 (norm) geometry: one CTA per row, front-loaded register pipeline.
#define K2_THREADS 512
#define K2_ITERS   5                          // ceil(2500/512)

// Per-(batch,time) channel means: 2.56 MB total; per-chunk slice 320 KB (hot).
__device__ float g_mu[B_DIM * T_DIM];

// ---------------------------------------------------------------------------
// mu for one chunk. Default (evict-normal) x loads: park the 41 MB chunk in
// L2 for the immediately-following norm_chunk. Lanes = consecutive quads ->
// 512B coalesced warp reads per channel step. Proven R12 geometry.
// ---------------------------------------------------------------------------
__global__ __launch_bounds__(K1_THREADS)
void mu_chunk(const float* __restrict__ x, int chunk) {
    __shared__ float4 part[K1_GPC][K1_QPC];     // 4 KB

    const int ql = threadIdx.x & (K1_QPC - 1);
    const int g  = threadIdx.x >> 5;            // channel group 0..7
    const int q  = chunk * CHUNK_QUADS + blockIdx.x * K1_QPC + ql;
    const int b  = q / T4;
    const int i4 = q - b * T4;

    const float4* __restrict__ xp =
        reinterpret_cast<const float4*>(x)
        + ((size_t)b * C_DIM + (size_t)g * K1_CPG) * T4 + i4;

    float sx = 0.f, sy = 0.f, sz = 0.f, sw = 0.f;
#pragma unroll
    for (int c = 0; c < K1_CPG; ++c) {
        float4 v = xp[(size_t)c * T4];          // evict-normal: park in L2
        sx += v.x; sy += v.y; sz += v.z; sw += v.w;
    }
    float4 p; p.x = sx; p.y = sy; p.z = sz; p.w = sw;
    part[g][ql] = p;
    __syncthreads();

    if (threadIdx.x < K1_QPC) {
        float4 a = part[0][ql];
#pragma unroll
        for (int gg = 1; gg < K1_GPC; ++gg) {
            float4 t = part[gg][ql];
            a.x += t.x; a.y += t.y; a.z += t.z; a.w += t.w;
        }
        const float inv = 1.0f / (float)C_DIM;
        a.x *= inv; a.y *= inv; a.z *= inv; a.w *= inv;
        reinterpret_cast<float4*>(g_mu)[(size_t)b * T4 + i4] = a;
    }
}

// ---------------------------------------------------------------------------
// norm for one chunk: one CTA per (b,c) row, ascending row order (oldest
// parked lines consumed first). d = x - mu held in registers across the
// block reduction (proven R6 geometry, 54 regs, 2 CTAs/SM). x via __ldcs
// (demotes the line after the L2 hit — consumed data self-evicts), mu
// default (hot 320 KB slice), out via __stcs (write stream self-evicts
// instead of displacing the parked chunk).
// ---------------------------------------------------------------------------
__global__ __launch_bounds__(K2_THREADS, 2)
void norm_chunk(const float* __restrict__ x, float* __restrict__ out, int chunk) {
    __shared__ float red_s[16], red_s2[16];
    __shared__ float s_mean, s_inv;

    const int row = chunk * CHUNK_ROWS + blockIdx.x;
    const int b   = row >> 7;

    const float4* __restrict__ xp =
        reinterpret_cast<const float4*>(x) + (size_t)row * T4;
    const float4* __restrict__ mp =
        reinterpret_cast<const float4*>(g_mu) + (size_t)b * T4;

    float4 xv[K2_ITERS], mv[K2_ITERS];
#pragma unroll
    for (int k = 0; k < K2_ITERS; ++k) {
        const int i = threadIdx.x + k * K2_THREADS;
        if (i < T4) {
            xv[k] = __ldcs(xp + i);
            mv[k] = mp[i];
        }
    }

    float s = 0.f, s2 = 0.f;
#pragma unroll
    for (int k = 0; k < K2_ITERS; ++k) {
        const int i = threadIdx.x + k * K2_THREADS;
        if (i < T4) {
            xv[k].x -= mv[k].x; xv[k].y -= mv[k].y;
            xv[k].z -= mv[k].z; xv[k].w -= mv[k].w;
            s  += xv[k].x + xv[k].y + xv[k].z + xv[k].w;
            s2 += xv[k].x * xv[k].x + xv[k].y * xv[k].y
                + xv[k].z * xv[k].z + xv[k].w * xv[k].w;
        }
    }

#pragma unroll
    for (int o = 16; o > 0; o >>= 1) {
        s  += __shfl_down_sync(0xffffffffu, s,  o);
        s2 += __shfl_down_sync(0xffffffffu, s2, o);
    }
    const int wid = threadIdx.x >> 5;
    const int lid = threadIdx.x & 31;
    if (lid == 0) { red_s[wid] = s; red_s2[wid] = s2; }
    __syncthreads();

    if (threadIdx.x < 32) {
        float a  = (lid < 16) ? red_s[lid]  : 0.f;
        float a2 = (lid < 16) ? red_s2[lid] : 0.f;
#pragma unroll
        for (int o = 8; o > 0; o >>= 1) {
            a  += __shfl_down_sync(0xffffffffu, a,  o);
            a2 += __shfl_down_sync(0xffffffffu, a2, o);
        }
        if (lid == 0) {
            const float invT = 1.0f / (float)T_DIM;
            float mean = a * invT;
            float var  = a2 * invT - mean * mean;
            float sd   = sqrtf(fmaxf(var, 0.0f));
            if (sd == 0.0f) sd = 1.0f;
            s_mean = mean;
            s_inv  = 1.0f / sd;
        }
    }
    __syncthreads();

    const float mean = s_mean;
    const float invs = s_inv;
    float4* __restrict__ op = reinterpret_cast<float4*>(out) + (size_t)row * T4;
#pragma unroll
    for (int k = 0; k < K2_ITERS; ++k) {
        const int i = threadIdx.x + k * K2_THREADS;
        if (i < T4) {
            float4 r;
            r.x = (xv[k].x - mean) * invs;
            r.y = (xv[k].y - mean) * invs;
            r.z = (xv[k].z - mean) * invs;
            r.w = (xv[k].w - mean) * invs;
            __stcs(op + i, r);
        }
    }
}

extern "C" void kernel_launch(void* const* d_in, const int* in_sizes, int n_in,
                              void* d_out, int out_size) {
    (void)in_sizes; (void)n_in; (void)out_size;
    const float* x   = (const float*)d_in[0];
    float*       out = (float*)d_out;

    for (int k = 0; k < NCHUNK; ++k) {
        mu_chunk<<<K1_GRID, K1_THREADS>>>(x, k);
        norm_chunk<<<CHUNK_ROWS, K2_THREADS>>>(x, out, k);
    }
}

// round 15
// speedup vs baseline: 1.4046x; 1.1749x over previous
#include <cuda_runtime.h>

// x: (B=64, C=128, T=10000) float32, row-major.
#define B_DIM 64
#define C_DIM 128
#define T_DIM 10000
#define T4    2500

// Chunking: 8 chunks of 8 batches (41 MB). Producer (mu of chunk k+1) and
// consumer (norm of chunk k) run CONCURRENTLY in one launch, roles interleaved
// by blockIdx so every wave mixes DRAM-read (mu) with DRAM-write (norm).
#define NCHUNK      8
#define B_PER_CHUNK (B_DIM / NCHUNK)          // 8
#define CHUNK_QUADS (B_PER_CHUNK * T4)        // 20000 float4
#define CHUNK_ROWS  (B_PER_CHUNK * C_DIM)     // 1024

#define THREADS 512

// Step-kernel grid: 128 groups x (8 norm + 5 mu) = 1024 norm + 640 mu CTAs.
#define GRP_NORM 8
#define GRP_MU   5
#define GRP_SZ   (GRP_NORM + GRP_MU)          // 13
#define NGROUPS  128
#define STEP_GRID (NGROUPS * GRP_SZ)          // 1664

// mu geometry (512 threads): 32 quads x 16 groups x 8 channels.
#define MU_QPC  32
#define MU_GPC  16
#define MU_CPG  8
#define MU_JOBS (CHUNK_QUADS / MU_QPC)        // 625 (15 of 640 CTAs idle)

// norm per-thread pipeline.
#define K2_ITERS 5                            // ceil(2500/512)

__device__ float g_mu[B_DIM * T_DIM];         // 2.56 MB, L2-hot

// ---------------------------------------------------------------------------
// mu role: park chunk `chunk` in L2 (evict-normal loads) while computing its
// channel means. job in [0, MU_JOBS). Lanes = consecutive quads -> 512B
// coalesced warp reads per channel step.
// ---------------------------------------------------------------------------
__device__ __forceinline__ void mu_body(const float* __restrict__ x,
                                        int chunk, int job) {
    __shared__ float4 part[MU_GPC][MU_QPC];   // 8 KB

    const int ql = threadIdx.x & 31;
    const int g  = threadIdx.x >> 5;          // 0..15
    const int q  = chunk * CHUNK_QUADS + job * MU_QPC + ql;
    const int b  = q / T4;
    const int i4 = q - b * T4;

    const float4* __restrict__ xp =
        reinterpret_cast<const float4*>(x)
        + ((size_t)b * C_DIM + (size_t)g * MU_CPG) * T4 + i4;

    float sx = 0.f, sy = 0.f, sz = 0.f, sw = 0.f;
#pragma unroll
    for (int c = 0; c < MU_CPG; ++c) {
        float4 v = xp[(size_t)c * T4];        // evict-normal: park in L2
        sx += v.x; sy += v.y; sz += v.z; sw += v.w;
    }
    float4 p; p.x = sx; p.y = sy; p.z = sz; p.w = sw;
    part[g][ql] = p;
    __syncthreads();

    if (threadIdx.x < MU_QPC) {
        float4 a = part[0][ql];
#pragma unroll
        for (int gg = 1; gg < MU_GPC; ++gg) {
            float4 t = part[gg][ql];
            a.x += t.x; a.y += t.y; a.z += t.z; a.w += t.w;
        }
        const float inv = 1.0f / (float)C_DIM;
        a.x *= inv; a.y *= inv; a.z *= inv; a.w *= inv;
        reinterpret_cast<float4*>(g_mu)[(size_t)b * T4 + i4] = a;
    }
}

// ---------------------------------------------------------------------------
// norm role: one CTA per (b,c) row of chunk `chunk`. Proven R6/R12 geometry:
// d = x - mu held in registers across the block reduction, front-loaded MLP.
// x via __ldcs (demote after the L2 hit), mu default, out via __stcs.
// ---------------------------------------------------------------------------
__device__ __forceinline__ void norm_body(const float* __restrict__ x,
                                          float* __restrict__ out,
                                          int chunk, int nrow) {
    __shared__ float red_s[16], red_s2[16];
    __shared__ float s_mean, s_inv;

    const int row = chunk * CHUNK_ROWS + nrow;
    const int b   = row >> 7;

    const float4* __restrict__ xp =
        reinterpret_cast<const float4*>(x) + (size_t)row * T4;
    const float4* __restrict__ mp =
        reinterpret_cast<const float4*>(g_mu) + (size_t)b * T4;

    float4 xv[K2_ITERS], mv[K2_ITERS];
#pragma unroll
    for (int k = 0; k < K2_ITERS; ++k) {
        const int i = threadIdx.x + k * THREADS;
        if (i < T4) {
            xv[k] = __ldcs(xp + i);
            mv[k] = mp[i];
        }
    }

    float s = 0.f, s2 = 0.f;
#pragma unroll
    for (int k = 0; k < K2_ITERS; ++k) {
        const int i = threadIdx.x + k * THREADS;
        if (i < T4) {
            xv[k].x -= mv[k].x; xv[k].y -= mv[k].y;
            xv[k].z -= mv[k].z; xv[k].w -= mv[k].w;
            s  += xv[k].x + xv[k].y + xv[k].z + xv[k].w;
            s2 += xv[k].x * xv[k].x + xv[k].y * xv[k].y
                + xv[k].z * xv[k].z + xv[k].w * xv[k].w;
        }
    }

#pragma unroll
    for (int o = 16; o > 0; o >>= 1) {
        s  += __shfl_down_sync(0xffffffffu, s,  o);
        s2 += __shfl_down_sync(0xffffffffu, s2, o);
    }
    const int wid = threadIdx.x >> 5;
    const int lid = threadIdx.x & 31;
    if (lid == 0) { red_s[wid] = s; red_s2[wid] = s2; }
    __syncthreads();

    if (threadIdx.x < 32) {
        float a  = (lid < 16) ? red_s[lid]  : 0.f;
        float a2 = (lid < 16) ? red_s2[lid] : 0.f;
#pragma unroll
        for (int o = 8; o > 0; o >>= 1) {
            a  += __shfl_down_sync(0xffffffffu, a,  o);
            a2 += __shfl_down_sync(0xffffffffu, a2, o);
        }
        if (lid == 0) {
            const float invT = 1.0f / (float)T_DIM;
            float mean = a * invT;
            float var  = a2 * invT - mean * mean;
            float sd   = sqrtf(fmaxf(var, 0.0f));
            if (sd == 0.0f) sd = 1.0f;
            s_mean = mean;
            s_inv  = 1.0f / sd;
        }
    }
    __syncthreads();

    const float mean = s_mean;
    const float invs = s_inv;
    float4* __restrict__ op = reinterpret_cast<float4*>(out) + (size_t)row * T4;
#pragma unroll
    for (int k = 0; k < K2_ITERS; ++k) {
        const int i = threadIdx.x + k * THREADS;
        if (i < T4) {
            float4 r;
            r.x = (xv[k].x - mean) * invs;
            r.y = (xv[k].y - mean) * invs;
            r.z = (xv[k].z - mean) * invs;
            r.w = (xv[k].w - mean) * invs;
            __stcs(op + i, r);
        }
    }
}

// ---------------------------------------------------------------------------
// Mixed step: norm(chunk) and mu(chunk+1) interleaved 8:5 by blockIdx so the
// HW work distributor mixes DRAM-writers and DRAM-readers in every wave.
// ---------------------------------------------------------------------------
__global__ __launch_bounds__(THREADS, 2)
void step_kernel(const float* __restrict__ x, float* __restrict__ out,
                 int chunk) {
    const int grp = blockIdx.x / GRP_SZ;
    const int pos = blockIdx.x - grp * GRP_SZ;
    if (pos < GRP_NORM) {
        norm_body(x, out, chunk, grp * GRP_NORM + pos);
    } else {
        const int job = grp * GRP_MU + (pos - GRP_NORM);
        if (job < MU_JOBS) mu_body(x, chunk + 1, job);
    }
}

// Standalone mu (for chunk 0) and norm (for the last chunk).
__global__ __launch_bounds__(THREADS, 2)
void mu_kernel(const float* __restrict__ x, int chunk) {
    if (blockIdx.x < MU_JOBS) mu_body(x, chunk, blockIdx.x);
}

__global__ __launch_bounds__(THREADS, 2)
void norm_kernel(const float* __restrict__ x, float* __restrict__ out,
                 int chunk) {
    norm_body(x, out, chunk, blockIdx.x);
}

extern "C" void kernel_launch(void* const* d_in, const int* in_sizes, int n_in,
                              void* d_out, int out_size) {
    (void)in_sizes; (void)n_in; (void)out_size;
    const float* x   = (const float*)d_in[0];
    float*       out = (float*)d_out;

    mu_kernel<<<MU_JOBS, THREADS>>>(x, 0);
    for (int k = 0; k < NCHUNK - 1; ++k)
        step_kernel<<<STEP_GRID, THREADS>>>(x, out, k);
    norm_kernel<<<CHUNK_ROWS, THREADS>>>(x, out, NCHUNK - 1);
}